// round 7
// baseline (speedup 1.0000x reference)
#include <cuda_runtime.h>
#include <cuda_fp16.h>
#include <math.h>

#define NN 50000
#define NE 1600000
#define NB 196          // ceil(NN/256)

// ---------------- scratch -----------------------------------------------------
__device__ __half d_Qh[NN * 256];       // [n][pair(16)][c(16)] q pre-scaled by 0.25*log2e
// KV row (1024B) chunk-interleaved: half index = n*512 + (j)*128 + pair*8 + (c&7)
//   j = (c>>3) for K, 2+(c>>3) for V.  Lane p reads uint4 base[j*16 + p].
__device__ __half d_KV[NN * 512];
__device__ float  d_H[NN * 256];        // skip first, then h (post-ELU)
__device__ float  d_HW[NN * 32];
__device__ float4 d_csr[NE];            // {src(int bits), ax, ay, dis[src]*ay}
__device__ int    d_count[NN];
__device__ int    d_cursor[NN];
__device__ int    d_offsets[NN + 1];
__device__ int    d_bsum[NB];
__device__ int    d_boff[NB];
__device__ float  d_degw[NN];
__device__ float  d_dis[NN];

__device__ __forceinline__ float ex2f(float x) {
    float y; asm("ex2.approx.f32 %0, %1;" : "=f"(y) : "f"(x)); return y;
}
__device__ __forceinline__ __half2 h2(unsigned u) { return *(__half2*)&u; }

// ---------------- CSR build ---------------------------------------------------
__global__ void zero_kernel() {
    int i = blockIdx.x * blockDim.x + threadIdx.x;
    if (i < NN) { d_count[i] = 0; d_cursor[i] = 0; d_degw[i] = 0.f; }
}

__global__ void hist_kernel(const int* __restrict__ ei, const float* __restrict__ ea) {
    int e = blockIdx.x * blockDim.x + threadIdx.x;
    if (e < NE) {
        int dst = ei[NE + e];
        atomicAdd(&d_count[dst], 1);
        atomicAdd(&d_degw[dst], ea[2 * e + 1]);
    }
}

__global__ void scanA_kernel() {
    __shared__ int ws[8];
    int tid = threadIdx.x, lane = tid & 31, wid = tid >> 5;
    int i = blockIdx.x * 256 + tid;
    int v = (i < NN) ? d_count[i] : 0;
    int s = v;
    #pragma unroll
    for (int off = 1; off < 32; off <<= 1) {
        int t = __shfl_up_sync(0xffffffffu, s, off);
        if (lane >= off) s += t;
    }
    if (lane == 31) ws[wid] = s;
    __syncthreads();
    if (tid < 8) {
        int t = ws[tid];
        #pragma unroll
        for (int off = 1; off < 8; off <<= 1) {
            int u = __shfl_up_sync(0xffu, t, off);
            if (tid >= off) t += u;
        }
        ws[tid] = t;
    }
    __syncthreads();
    int wexcl = wid ? ws[wid - 1] : 0;
    if (i < NN) d_offsets[i] = wexcl + s - v;
    if (tid == 0) d_bsum[blockIdx.x] = ws[7];
}

__global__ void scanB_kernel() {
    __shared__ int ws[8];
    int tid = threadIdx.x, lane = tid & 31, wid = tid >> 5;
    int v = (tid < NB) ? d_bsum[tid] : 0;
    int s = v;
    #pragma unroll
    for (int off = 1; off < 32; off <<= 1) {
        int t = __shfl_up_sync(0xffffffffu, s, off);
        if (lane >= off) s += t;
    }
    if (lane == 31) ws[wid] = s;
    __syncthreads();
    if (tid < 8) {
        int t = ws[tid];
        #pragma unroll
        for (int off = 1; off < 8; off <<= 1) {
            int u = __shfl_up_sync(0xffu, t, off);
            if (tid >= off) t += u;
        }
        ws[tid] = t;
    }
    __syncthreads();
    int wexcl = wid ? ws[wid - 1] : 0;
    if (tid < NB) d_boff[tid] = wexcl + s - v;
}

__global__ void scanC_kernel() {
    int i = blockIdx.x * 256 + threadIdx.x;
    if (i < NN) {
        d_offsets[i] += d_boff[blockIdx.x];
        d_dis[i] = rsqrtf(d_degw[i] + 2.0f);
    }
    if (i == 0) d_offsets[NN] = NE;
}

__global__ void scatter_kernel(const int* __restrict__ ei, const float* __restrict__ ea) {
    int e = blockIdx.x * blockDim.x + threadIdx.x;
    if (e < NE) {
        int src = ei[e], dst = ei[NE + e];
        int pos = d_offsets[dst] + atomicAdd(&d_cursor[dst], 1);
        float ax = ea[2 * e], ay = ea[2 * e + 1];
        float4 pk;
        pk.x = __int_as_float(src);
        pk.y = ax;
        pk.z = ay;
        pk.w = d_dis[src] * ay;
        d_csr[pos] = pk;
    }
}

// ---------------- QKV + skip precompute ---------------------------------------
__global__ void qkv_kernel(const float* __restrict__ x,
                           const float* __restrict__ Wq, const float* __restrict__ bq,
                           const float* __restrict__ Wk, const float* __restrict__ bk,
                           const float* __restrict__ Wv, const float* __restrict__ bv,
                           const float* __restrict__ Wsk, const float* __restrict__ bsk) {
    int lane = threadIdx.x & 31;
    int warp = (blockIdx.x * blockDim.x + threadIdx.x) >> 5;
    int nwarps = (gridDim.x * blockDim.x) >> 5;
    float wq[8], wk[8], wv[8], ws[8];
    #pragma unroll
    for (int i = 0; i < 8; i++) {
        wq[i] = Wq[i * 32 + lane];
        wk[i] = Wk[i * 32 + lane];
        wv[i] = Wv[i * 32 + lane];
        ws[i] = Wsk[i * 32 + lane];
    }
    float bqv = bq[lane], bkv = bk[lane], bvv = bv[lane], bsv = bsk[lane];
    const float QS = 0.25f * 1.4426950408889634f;  // 1/sqrt(16) * log2(e)
    int h = lane >> 4, c = lane & 15;
    int cj = c >> 3, cr = c & 7;

    for (int n = warp; n < NN; n += nwarps) {
        float x0 = x[n * 64 + lane];
        float x1 = x[n * 64 + 32 + lane];
        #pragma unroll
        for (int b = 0; b < 8; b++) {
            float aq = bqv, ak = bkv, av = bvv, asv = bsv;
            #pragma unroll
            for (int i = 0; i < 8; i++) {
                const int f = b * 8 + i;
                float xv = __shfl_sync(0xffffffffu, (f < 32) ? x0 : x1, f & 31);
                aq += xv * wq[i]; ak += xv * wk[i]; av += xv * wv[i]; asv += xv * ws[i];
            }
            int pairIdx = b * 2 + h;
            d_Qh[n * 256 + pairIdx * 16 + c] = __float2half(aq * QS);
            // chunk-interleaved KV
            d_KV[n * 512 + cj * 128 + pairIdx * 8 + cr]         = __float2half(ak);
            d_KV[n * 512 + 256 + cj * 128 + pairIdx * 8 + cr]   = __float2half(av);
            d_H[n * 256 + pairIdx * 16 + c] = asv;
        }
    }
}

// ---------------- attention ---------------------------------------------------
// One warp per dst. Lane owns one (band,head) pair; half-warps split edges;
// 2-edge unroll per half-warp + csr software pipeline. KV loads COALESCED:
// lane p reads uint4 kvbase[j*16 + p], consecutive lanes -> consecutive 16B.
__device__ __forceinline__ __half2 dot8(uint4 a, uint4 b, const __half2* q) {
    __half2 d = __float2half2_rn(0.f);
    d = __hfma2(q[0], h2(a.x), d);
    d = __hfma2(q[1], h2(a.y), d);
    d = __hfma2(q[2], h2(a.z), d);
    d = __hfma2(q[3], h2(a.w), d);
    d = __hfma2(q[4], h2(b.x), d);
    d = __hfma2(q[5], h2(b.y), d);
    d = __hfma2(q[6], h2(b.z), d);
    d = __hfma2(q[7], h2(b.w), d);
    return d;
}

__global__ void __launch_bounds__(256, 3) attn_kernel(const float* __restrict__ We) {
    int tid = blockIdx.x * blockDim.x + threadIdx.x;
    int dst = tid >> 5;
    if (dst >= NN) return;
    int lane = threadIdx.x & 31;
    int pair = lane & 15, hf = lane >> 4;
    int hoff = (pair & 1) << 4;

    __half2 q[8];
    {
        const uint4* Qp = (const uint4*)&d_Qh[dst * 256 + pair * 16];
        uint4 qa = Qp[0], qb = Qp[1];
        q[0] = h2(qa.x); q[1] = h2(qa.y); q[2] = h2(qa.z); q[3] = h2(qa.w);
        q[4] = h2(qb.x); q[5] = h2(qb.y); q[6] = h2(qb.z); q[7] = h2(qb.w);
    }
    float qw0 = 0.f, qw1 = 0.f;
    #pragma unroll
    for (int i = 0; i < 8; i++) {
        float2 qf = __half22float2(q[i]);
        qw0 += qf.x * We[hoff + 2 * i]      + qf.y * We[hoff + 2 * i + 1];
        qw1 += qf.x * We[32 + hoff + 2 * i] + qf.y * We[32 + hoff + 2 * i + 1];
    }

    __half2 acch[8];
    #pragma unroll
    for (int i = 0; i < 8; i++) acch[i] = __float2half2_rn(0.f);
    float sax = 0.f, say = 0.f, z = 0.f;

    int start = d_offsets[dst], end = d_offsets[dst + 1];
    int last = end - 1;

    float4 pkA, pkB;
    if (start < end) {
        pkA = d_csr[min(start + hf, last)];
        pkB = d_csr[min(start + hf + 2, last)];
    }
    for (int e = start + hf; e < end; e += 4) {
        float4 cA = pkA, cB = pkB;
        bool hasB = (e + 2 < end);
        pkA = d_csr[min(e + 4, last)];
        pkB = d_csr[min(e + 6, last)];

        int srcA = __float_as_int(cA.x);
        int srcB = __float_as_int(cB.x);
        const uint4* pA = (const uint4*)&d_KV[srcA * 512];
        uint4 ka0 = pA[pair], ka1 = pA[16 + pair], va0 = pA[32 + pair], va1 = pA[48 + pair];
        const uint4* pB = (const uint4*)&d_KV[srcB * 512];
        uint4 kb0 = pB[pair], kb1 = pB[16 + pair], vb0 = pB[32 + pair], vb1 = pB[48 + pair];

        float2 dA = __half22float2(dot8(ka0, ka1, q));
        float pAf = ex2f(dA.x + dA.y + cA.y * qw0 + cA.z * qw1);
        float2 dB = __half22float2(dot8(kb0, kb1, q));
        float pBf = hasB ? ex2f(dB.x + dB.y + cB.y * qw0 + cB.z * qw1) : 0.f;

        z += pAf + pBf;
        sax = fmaf(pAf, cA.y, sax); sax = fmaf(pBf, cB.y, sax);
        say = fmaf(pAf, cA.z, say); say = fmaf(pBf, cB.z, say);

        __half2 pA2 = __float2half2_rn(pAf);
        __half2 pB2 = __float2half2_rn(pBf);
        acch[0] = __hfma2(pA2, h2(va0.x), acch[0]);
        acch[1] = __hfma2(pA2, h2(va0.y), acch[1]);
        acch[2] = __hfma2(pA2, h2(va0.z), acch[2]);
        acch[3] = __hfma2(pA2, h2(va0.w), acch[3]);
        acch[4] = __hfma2(pA2, h2(va1.x), acch[4]);
        acch[5] = __hfma2(pA2, h2(va1.y), acch[5]);
        acch[6] = __hfma2(pA2, h2(va1.z), acch[6]);
        acch[7] = __hfma2(pA2, h2(va1.w), acch[7]);
        acch[0] = __hfma2(pB2, h2(vb0.x), acch[0]);
        acch[1] = __hfma2(pB2, h2(vb0.y), acch[1]);
        acch[2] = __hfma2(pB2, h2(vb0.z), acch[2]);
        acch[3] = __hfma2(pB2, h2(vb0.w), acch[3]);
        acch[4] = __hfma2(pB2, h2(vb1.x), acch[4]);
        acch[5] = __hfma2(pB2, h2(vb1.y), acch[5]);
        acch[6] = __hfma2(pB2, h2(vb1.z), acch[6]);
        acch[7] = __hfma2(pB2, h2(vb1.w), acch[7]);
    }

    float accf[16];
    #pragma unroll
    for (int i = 0; i < 8; i++) {
        float2 t = __half22float2(acch[i]);
        accf[2 * i] = t.x; accf[2 * i + 1] = t.y;
    }
    z   += __shfl_xor_sync(0xffffffffu, z, 16);
    sax += __shfl_xor_sync(0xffffffffu, sax, 16);
    say += __shfl_xor_sync(0xffffffffu, say, 16);
    #pragma unroll
    for (int c = 0; c < 16; c++) accf[c] += __shfl_xor_sync(0xffffffffu, accf[c], 16);

    if (hf == 0) {
        float rz = (z > 0.f) ? 1.0f / z : 0.f;
        float* Hp = &d_H[dst * 256 + pair * 16];
        float o[16];
        #pragma unroll
        for (int c = 0; c < 16; c++) {
            float w0 = We[hoff + c], w1 = We[32 + hoff + c];
            float a = accf[c] + sax * w0 + say * w1;
            float t = fmaf(a, rz, Hp[c]);
            o[c] = (t > 0.f) ? t : 0.1f * (__expf(t) - 1.0f);
        }
        float4* Op = (float4*)Hp;
        Op[0] = make_float4(o[0], o[1], o[2], o[3]);
        Op[1] = make_float4(o[4], o[5], o[6], o[7]);
        Op[2] = make_float4(o[8], o[9], o[10], o[11]);
        Op[3] = make_float4(o[12], o[13], o[14], o[15]);
    }
}

// ---------------- hw = h @ Wg -------------------------------------------------
__global__ void hw_kernel(const float* __restrict__ Wg) {
    __shared__ float wgs[256 * 32];
    for (int idx = threadIdx.x; idx < 8192; idx += blockDim.x)
        wgs[idx] = Wg[idx];
    __syncthreads();
    int lane = threadIdx.x & 31;
    int warp = (blockIdx.x * blockDim.x + threadIdx.x) >> 5;
    int nwarps = (gridDim.x * blockDim.x) >> 5;
    for (int n = warp; n < NN; n += nwarps) {
        const float4* Hp = (const float4*)&d_H[n * 256];
        float a = 0.f;
        #pragma unroll
        for (int c = 0; c < 64; c++) {
            float4 hv = Hp[c];
            a += hv.x * wgs[(4 * c + 0) * 32 + lane];
            a += hv.y * wgs[(4 * c + 1) * 32 + lane];
            a += hv.z * wgs[(4 * c + 2) * 32 + lane];
            a += hv.w * wgs[(4 * c + 3) * 32 + lane];
        }
        d_HW[n * 32 + lane] = a;
    }
}

// ---------------- final normalized propagation --------------------------------
__global__ void final_kernel(const float* __restrict__ bg, float* __restrict__ out) {
    int lane = threadIdx.x & 31;
    int dst = (blockIdx.x * blockDim.x + threadIdx.x) >> 5;
    if (dst >= NN) return;
    float dd = d_dis[dst];
    float acc = 2.0f * dd * d_HW[dst * 32 + lane];  // self loop
    int start = d_offsets[dst], end = d_offsets[dst + 1];
    int last = end - 1;
    for (int t = start; t < end; t += 4) {
        float4 c0 = d_csr[t];
        float4 c1 = d_csr[min(t + 1, last)];
        float4 c2 = d_csr[min(t + 2, last)];
        float4 c3 = d_csr[min(t + 3, last)];
        float w0 = c0.w;
        float w1 = (t + 1 < end) ? c1.w : 0.f;
        float w2 = (t + 2 < end) ? c2.w : 0.f;
        float w3 = (t + 3 < end) ? c3.w : 0.f;
        float v0 = d_HW[__float_as_int(c0.x) * 32 + lane];
        float v1 = d_HW[__float_as_int(c1.x) * 32 + lane];
        float v2 = d_HW[__float_as_int(c2.x) * 32 + lane];
        float v3 = d_HW[__float_as_int(c3.x) * 32 + lane];
        acc = fmaf(w0, v0, acc);
        acc = fmaf(w1, v1, acc);
        acc = fmaf(w2, v2, acc);
        acc = fmaf(w3, v3, acc);
    }
    out[dst * 32 + lane] = bg[lane] + dd * acc;
}

// ---------------- launch -----------------------------------------------------
extern "C" void kernel_launch(void* const* d_in, const int* in_sizes, int n_in,
                              void* d_out, int out_size) {
    const float* x   = (const float*)d_in[0];
    const float* ea  = (const float*)d_in[1];
    const float* Wq  = (const float*)d_in[2];
    const float* bq  = (const float*)d_in[3];
    const float* Wk  = (const float*)d_in[4];
    const float* bk  = (const float*)d_in[5];
    const float* Wv  = (const float*)d_in[6];
    const float* bv  = (const float*)d_in[7];
    const float* We  = (const float*)d_in[8];
    const float* Wsk = (const float*)d_in[9];
    const float* bsk = (const float*)d_in[10];
    const float* Wg  = (const float*)d_in[11];
    const float* bg  = (const float*)d_in[12];
    const int*   ei  = (const int*)d_in[13];
    float* out = (float*)d_out;

    zero_kernel<<<(NN + 255) / 256, 256>>>();
    hist_kernel<<<(NE + 255) / 256, 256>>>(ei, ea);
    scanA_kernel<<<NB, 256>>>();
    scanB_kernel<<<1, 256>>>();
    scanC_kernel<<<NB, 256>>>();
    scatter_kernel<<<(NE + 255) / 256, 256>>>(ei, ea);
    qkv_kernel<<<400, 256>>>(x, Wq, bq, Wk, bk, Wv, bv, Wsk, bsk);
    attn_kernel<<<(NN * 32 + 255) / 256, 256>>>(We);
    hw_kernel<<<296, 256>>>(Wg);
    final_kernel<<<(NN * 32 + 255) / 256, 256>>>(bg, out);
}

// round 8
// speedup vs baseline: 1.1692x; 1.1692x over previous
#include <cuda_runtime.h>
#include <cuda_fp16.h>
#include <math.h>

#define NN 50000
#define NE 1600000
#define NB 196             // ceil(NN/256)
#define SCAT_BLOCKS 6250   // ceil(NE/256)
#define QKV_BLOCKS 400

// ---------------- scratch -----------------------------------------------------
__device__ __half d_Qh[NN * 256];       // [n][pair(16)][c(16)] q pre-scaled by 0.25*log2e
__device__ __half d_KV[NN * 512];       // [n][pair(16)][K 16 | V 16] fp16
__device__ float  d_H[NN * 256];        // skip first, then h (post-ELU)
__device__ float  d_HW[NN * 32];
__device__ float4 d_csr[NE];            // {src(int bits), ax, ay, dis[src]*ay}
__device__ int    d_count[NN];          // zero at replay start (BSS / reset below)
__device__ int    d_cursor[NN];
__device__ int    d_offsets[NN + 1];
__device__ float  d_degw[NN];
__device__ float  d_dis[NN];

__device__ __forceinline__ float ex2f(float x) {
    float y; asm("ex2.approx.f32 %0, %1;" : "=f"(y) : "f"(x)); return y;
}
__device__ __forceinline__ __half2 h2(unsigned u) { return *(__half2*)&u; }

// ---------------- 0: histogram (counters pre-zeroed by previous replay) -------
__global__ void hist_kernel(const int* __restrict__ ei, const float* __restrict__ ea) {
    int e = blockIdx.x * blockDim.x + threadIdx.x;
    if (e < NE) {
        int dst = ei[NE + e];
        atomicAdd(&d_count[dst], 1);
        atomicAdd(&d_degw[dst], ea[2 * e + 1]);
    }
}

// ---------------- 1: fused scan (carry recomputed per block) + dis ------------
__global__ void scan_fused() {
    __shared__ int wsum[8];
    __shared__ int s_carry;
    int tid = threadIdx.x, lane = tid & 31, wid = tid >> 5;
    int b = blockIdx.x;

    // carry = sum of counts in all previous chunks
    int carry = 0;
    for (int i = tid; i < b * 256; i += 256) carry += d_count[i];
    #pragma unroll
    for (int off = 16; off; off >>= 1) carry += __shfl_xor_sync(0xffffffffu, carry, off);
    if (lane == 0) wsum[wid] = carry;
    __syncthreads();
    if (tid == 0) {
        int c = 0;
        #pragma unroll
        for (int i = 0; i < 8; i++) c += wsum[i];
        s_carry = c;
    }
    __syncthreads();

    // chunk-local exclusive scan
    int i = b * 256 + tid;
    int v = (i < NN) ? d_count[i] : 0;
    int s = v;
    #pragma unroll
    for (int off = 1; off < 32; off <<= 1) {
        int t = __shfl_up_sync(0xffffffffu, s, off);
        if (lane >= off) s += t;
    }
    if (lane == 31) wsum[wid] = s;
    __syncthreads();
    if (tid < 8) {
        int t = wsum[tid];
        #pragma unroll
        for (int off = 1; off < 8; off <<= 1) {
            int u = __shfl_up_sync(0xffu, t, off);
            if (tid >= off) t += u;
        }
        wsum[tid] = t;
    }
    __syncthreads();
    int wexcl = wid ? wsum[wid - 1] : 0;
    if (i < NN) {
        d_offsets[i] = s_carry + wexcl + s - v;
        d_dis[i] = rsqrtf(d_degw[i] + 2.0f);
    }
    if (b == 0 && tid == 0) d_offsets[NN] = NE;
}

// ---------------- 2: fused scatter + qkv --------------------------------------
__global__ void scatter_qkv_kernel(const int* __restrict__ ei, const float* __restrict__ ea,
                                   const float* __restrict__ x,
                                   const float* __restrict__ Wq, const float* __restrict__ bq,
                                   const float* __restrict__ Wk, const float* __restrict__ bk,
                                   const float* __restrict__ Wv, const float* __restrict__ bv,
                                   const float* __restrict__ Wsk, const float* __restrict__ bsk) {
    int b = blockIdx.x;
    if (b < SCAT_BLOCKS) {
        int e = b * 256 + threadIdx.x;
        // reset counters for the NEXT replay (scan_fused already consumed them)
        if (e < NN) { d_count[e] = 0; d_degw[e] = 0.f; }
        if (e < NE) {
            int src = ei[e], dst = ei[NE + e];
            int pos = d_offsets[dst] + atomicAdd(&d_cursor[dst], 1);
            float ax = ea[2 * e], ay = ea[2 * e + 1];
            float4 pk;
            pk.x = __int_as_float(src);
            pk.y = ax;
            pk.z = ay;
            pk.w = d_dis[src] * ay;
            d_csr[pos] = pk;
        }
    } else {
        int lane = threadIdx.x & 31;
        int warp = ((b - SCAT_BLOCKS) * 256 + threadIdx.x) >> 5;
        const int nwarps = QKV_BLOCKS * 8;
        float wq[8], wk[8], wv[8], ws[8];
        #pragma unroll
        for (int i = 0; i < 8; i++) {
            wq[i] = Wq[i * 32 + lane];
            wk[i] = Wk[i * 32 + lane];
            wv[i] = Wv[i * 32 + lane];
            ws[i] = Wsk[i * 32 + lane];
        }
        float bqv = bq[lane], bkv = bk[lane], bvv = bv[lane], bsv = bsk[lane];
        const float QS = 0.25f * 1.4426950408889634f;  // 1/sqrt(16) * log2(e)
        int h = lane >> 4, c = lane & 15;

        for (int n = warp; n < NN; n += nwarps) {
            float x0 = x[n * 64 + lane];
            float x1 = x[n * 64 + 32 + lane];
            #pragma unroll
            for (int bb = 0; bb < 8; bb++) {
                float aq = bqv, ak = bkv, av = bvv, asv = bsv;
                #pragma unroll
                for (int i = 0; i < 8; i++) {
                    const int f = bb * 8 + i;
                    float xv = __shfl_sync(0xffffffffu, (f < 32) ? x0 : x1, f & 31);
                    aq += xv * wq[i]; ak += xv * wk[i]; av += xv * wv[i]; asv += xv * ws[i];
                }
                int pairIdx = bb * 2 + h;
                d_Qh[n * 256 + pairIdx * 16 + c] = __float2half(aq * QS);
                d_KV[n * 512 + pairIdx * 32 + c]      = __float2half(ak);
                d_KV[n * 512 + pairIdx * 32 + 16 + c] = __float2half(av);
                d_H[n * 256 + pairIdx * 16 + c] = asv;
            }
        }
    }
}

// ---------------- 3: attention (PROFILED SLOT) --------------------------------
// One warp per dst. Lane owns one (band,head) pair; half-warps split edges;
// 2-edge unroll per half-warp -> 4 edges in flight per warp.
__device__ __forceinline__ __half2 dot8(uint4 a, uint4 b, const __half2* q) {
    __half2 d = __float2half2_rn(0.f);
    d = __hfma2(q[0], h2(a.x), d);
    d = __hfma2(q[1], h2(a.y), d);
    d = __hfma2(q[2], h2(a.z), d);
    d = __hfma2(q[3], h2(a.w), d);
    d = __hfma2(q[4], h2(b.x), d);
    d = __hfma2(q[5], h2(b.y), d);
    d = __hfma2(q[6], h2(b.z), d);
    d = __hfma2(q[7], h2(b.w), d);
    return d;
}

__global__ void __launch_bounds__(256, 2) attn_kernel(const float* __restrict__ We) {
    int tid = blockIdx.x * blockDim.x + threadIdx.x;
    int dst = tid >> 5;
    if (dst >= NN) return;
    int lane = threadIdx.x & 31;
    int pair = lane & 15, hf = lane >> 4;
    int hoff = (pair & 1) << 4;

    __half2 q[8];
    {
        const uint4* Qp = (const uint4*)&d_Qh[dst * 256 + pair * 16];
        uint4 qa = Qp[0], qb = Qp[1];
        q[0] = h2(qa.x); q[1] = h2(qa.y); q[2] = h2(qa.z); q[3] = h2(qa.w);
        q[4] = h2(qb.x); q[5] = h2(qb.y); q[6] = h2(qb.z); q[7] = h2(qb.w);
    }
    float qw0 = 0.f, qw1 = 0.f;
    #pragma unroll
    for (int i = 0; i < 8; i++) {
        float2 qf = __half22float2(q[i]);
        qw0 += qf.x * We[hoff + 2 * i]      + qf.y * We[hoff + 2 * i + 1];
        qw1 += qf.x * We[32 + hoff + 2 * i] + qf.y * We[32 + hoff + 2 * i + 1];
    }

    __half2 acch[8];
    #pragma unroll
    for (int i = 0; i < 8; i++) acch[i] = __float2half2_rn(0.f);
    float sax = 0.f, say = 0.f, z = 0.f;

    int start = d_offsets[dst], end = d_offsets[dst + 1];
    for (int e = start + hf; e < end; e += 4) {
        int eB = e + 2;
        bool hasB = (eB < end);
        float4 pkA = d_csr[e];
        float4 pkB = d_csr[hasB ? eB : e];
        int srcA = __float_as_int(pkA.x);
        int srcB = __float_as_int(pkB.x);
        const uint4* pA = (const uint4*)&d_KV[srcA * 512 + pair * 32];
        uint4 ka0 = pA[0], ka1 = pA[1], va0 = pA[2], va1 = pA[3];
        const uint4* pB = (const uint4*)&d_KV[srcB * 512 + pair * 32];
        uint4 kb0 = pB[0], kb1 = pB[1], vb0 = pB[2], vb1 = pB[3];

        float2 dA = __half22float2(dot8(ka0, ka1, q));
        float pAf = ex2f(dA.x + dA.y + pkA.y * qw0 + pkA.z * qw1);
        float2 dB = __half22float2(dot8(kb0, kb1, q));
        float pBf = hasB ? ex2f(dB.x + dB.y + pkB.y * qw0 + pkB.z * qw1) : 0.f;

        z += pAf + pBf;
        sax = fmaf(pAf, pkA.y, sax); sax = fmaf(pBf, pkB.y, sax);
        say = fmaf(pAf, pkA.z, say); say = fmaf(pBf, pkB.z, say);

        __half2 pA2 = __float2half2_rn(pAf);
        __half2 pB2 = __float2half2_rn(pBf);
        acch[0] = __hfma2(pA2, h2(va0.x), acch[0]);
        acch[1] = __hfma2(pA2, h2(va0.y), acch[1]);
        acch[2] = __hfma2(pA2, h2(va0.z), acch[2]);
        acch[3] = __hfma2(pA2, h2(va0.w), acch[3]);
        acch[4] = __hfma2(pA2, h2(va1.x), acch[4]);
        acch[5] = __hfma2(pA2, h2(va1.y), acch[5]);
        acch[6] = __hfma2(pA2, h2(va1.z), acch[6]);
        acch[7] = __hfma2(pA2, h2(va1.w), acch[7]);
        acch[0] = __hfma2(pB2, h2(vb0.x), acch[0]);
        acch[1] = __hfma2(pB2, h2(vb0.y), acch[1]);
        acch[2] = __hfma2(pB2, h2(vb0.z), acch[2]);
        acch[3] = __hfma2(pB2, h2(vb0.w), acch[3]);
        acch[4] = __hfma2(pB2, h2(vb1.x), acch[4]);
        acch[5] = __hfma2(pB2, h2(vb1.y), acch[5]);
        acch[6] = __hfma2(pB2, h2(vb1.z), acch[6]);
        acch[7] = __hfma2(pB2, h2(vb1.w), acch[7]);
    }

    float accf[16];
    #pragma unroll
    for (int i = 0; i < 8; i++) {
        float2 t = __half22float2(acch[i]);
        accf[2 * i] = t.x; accf[2 * i + 1] = t.y;
    }
    z   += __shfl_xor_sync(0xffffffffu, z, 16);
    sax += __shfl_xor_sync(0xffffffffu, sax, 16);
    say += __shfl_xor_sync(0xffffffffu, say, 16);
    #pragma unroll
    for (int c = 0; c < 16; c++) accf[c] += __shfl_xor_sync(0xffffffffu, accf[c], 16);

    if (hf == 0) {
        float rz = (z > 0.f) ? 1.0f / z : 0.f;
        float* Hp = &d_H[dst * 256 + pair * 16];
        float o[16];
        #pragma unroll
        for (int c = 0; c < 16; c++) {
            float w0 = We[hoff + c], w1 = We[32 + hoff + c];
            float a = accf[c] + sax * w0 + say * w1;
            float t = fmaf(a, rz, Hp[c]);
            o[c] = (t > 0.f) ? t : 0.1f * (__expf(t) - 1.0f);
        }
        float4* Op = (float4*)Hp;
        Op[0] = make_float4(o[0], o[1], o[2], o[3]);
        Op[1] = make_float4(o[4], o[5], o[6], o[7]);
        Op[2] = make_float4(o[8], o[9], o[10], o[11]);
        Op[3] = make_float4(o[12], o[13], o[14], o[15]);
    }
}

// ---------------- 4: hw = h @ Wg (+ cursor reset for next replay) -------------
__global__ void hw_kernel(const float* __restrict__ Wg) {
    __shared__ float wgs[256 * 32];
    int gid = blockIdx.x * blockDim.x + threadIdx.x;
    if (gid < NN) d_cursor[gid] = 0;   // reset for next replay's scatter
    for (int idx = threadIdx.x; idx < 8192; idx += blockDim.x)
        wgs[idx] = Wg[idx];
    __syncthreads();
    int lane = threadIdx.x & 31;
    int warp = gid >> 5;
    int nwarps = (gridDim.x * blockDim.x) >> 5;
    for (int n = warp; n < NN; n += nwarps) {
        const float4* Hp = (const float4*)&d_H[n * 256];
        float a = 0.f;
        #pragma unroll
        for (int c = 0; c < 64; c++) {
            float4 hv = Hp[c];
            a += hv.x * wgs[(4 * c + 0) * 32 + lane];
            a += hv.y * wgs[(4 * c + 1) * 32 + lane];
            a += hv.z * wgs[(4 * c + 2) * 32 + lane];
            a += hv.w * wgs[(4 * c + 3) * 32 + lane];
        }
        d_HW[n * 32 + lane] = a;
    }
}

// ---------------- 5: final normalized propagation -----------------------------
__global__ void final_kernel(const float* __restrict__ bg, float* __restrict__ out) {
    int lane = threadIdx.x & 31;
    int dst = (blockIdx.x * blockDim.x + threadIdx.x) >> 5;
    if (dst >= NN) return;
    float dd = d_dis[dst];
    float acc = 2.0f * dd * d_HW[dst * 32 + lane];  // self loop
    int start = d_offsets[dst], end = d_offsets[dst + 1];
    int last = end - 1;
    for (int t = start; t < end; t += 4) {
        float4 c0 = d_csr[t];
        float4 c1 = d_csr[min(t + 1, last)];
        float4 c2 = d_csr[min(t + 2, last)];
        float4 c3 = d_csr[min(t + 3, last)];
        float w0 = c0.w;
        float w1 = (t + 1 < end) ? c1.w : 0.f;
        float w2 = (t + 2 < end) ? c2.w : 0.f;
        float w3 = (t + 3 < end) ? c3.w : 0.f;
        float v0 = d_HW[__float_as_int(c0.x) * 32 + lane];
        float v1 = d_HW[__float_as_int(c1.x) * 32 + lane];
        float v2 = d_HW[__float_as_int(c2.x) * 32 + lane];
        float v3 = d_HW[__float_as_int(c3.x) * 32 + lane];
        acc = fmaf(w0, v0, acc);
        acc = fmaf(w1, v1, acc);
        acc = fmaf(w2, v2, acc);
        acc = fmaf(w3, v3, acc);
    }
    out[dst * 32 + lane] = bg[lane] + dd * acc;
}

// ---------------- launch -----------------------------------------------------
extern "C" void kernel_launch(void* const* d_in, const int* in_sizes, int n_in,
                              void* d_out, int out_size) {
    const float* x   = (const float*)d_in[0];
    const float* ea  = (const float*)d_in[1];
    const float* Wq  = (const float*)d_in[2];
    const float* bq  = (const float*)d_in[3];
    const float* Wk  = (const float*)d_in[4];
    const float* bk  = (const float*)d_in[5];
    const float* Wv  = (const float*)d_in[6];
    const float* bv  = (const float*)d_in[7];
    const float* We  = (const float*)d_in[8];
    const float* Wsk = (const float*)d_in[9];
    const float* bsk = (const float*)d_in[10];
    const float* Wg  = (const float*)d_in[11];
    const float* bg  = (const float*)d_in[12];
    const int*   ei  = (const int*)d_in[13];
    float* out = (float*)d_out;

    hist_kernel<<<SCAT_BLOCKS, 256>>>(ei, ea);                       // launch 0
    scan_fused<<<NB, 256>>>();                                       // launch 1
    scatter_qkv_kernel<<<SCAT_BLOCKS + QKV_BLOCKS, 256>>>(            // launch 2
        ei, ea, x, Wq, bq, Wk, bk, Wv, bv, Wsk, bsk);
    attn_kernel<<<(NN * 32 + 255) / 256, 256>>>(We);                 // launch 3 (profiled)
    hw_kernel<<<296, 256>>>(Wg);                                     // launch 4
    final_kernel<<<(NN * 32 + 255) / 256, 256>>>(bg, out);           // launch 5
}

// round 9
// speedup vs baseline: 1.8030x; 1.5421x over previous
#include <cuda_runtime.h>
#include <cuda_fp16.h>
#include <math.h>

#define NN 50000
#define NE 1600000
#define NB 196             // ceil(NN/256)
#define SCAT_BLOCKS 6250   // ceil(NE/256)
#define QKV_BLOCKS 400

// ---------------- scratch -----------------------------------------------------
__device__ __half d_Qh[NN * 256];       // [n][lane(32)][8ch]  (lane = pair*2+half)
// KV row = 1024B: first 512B = K half-slices ordered by lane, second 512B = V.
__device__ __half d_KV[NN * 512];
__device__ float  d_H[NN * 256];        // skip first, then h (post-ELU); [n][lane][8]
__device__ float  d_HW[NN * 32];
__device__ float4 d_csr[NE];            // {src(int bits), ax, ay, dis[src]*ay}
__device__ int    d_count[NN];          // zeroed for next replay inside scatter_qkv
__device__ int    d_cursor[NN];
__device__ int    d_offsets[NN + 1];
__device__ float  d_degw[NN];
__device__ float  d_dis[NN];

__device__ __forceinline__ float ex2f(float x) {
    float y; asm("ex2.approx.f32 %0, %1;" : "=f"(y) : "f"(x)); return y;
}
__device__ __forceinline__ __half2 h2(unsigned u) { return *(__half2*)&u; }

// ---------------- 0: histogram ------------------------------------------------
__global__ void hist_kernel(const int* __restrict__ ei, const float* __restrict__ ea) {
    int e = blockIdx.x * blockDim.x + threadIdx.x;
    if (e < NE) {
        int dst = ei[NE + e];
        atomicAdd(&d_count[dst], 1);
        atomicAdd(&d_degw[dst], ea[2 * e + 1]);
    }
}

// ---------------- 1: fused scan + dis -----------------------------------------
__global__ void scan_fused() {
    __shared__ int wsum[8];
    __shared__ int s_carry;
    int tid = threadIdx.x, lane = tid & 31, wid = tid >> 5;
    int b = blockIdx.x;

    int carry = 0;
    for (int i = tid; i < b * 256; i += 256) carry += d_count[i];
    #pragma unroll
    for (int off = 16; off; off >>= 1) carry += __shfl_xor_sync(0xffffffffu, carry, off);
    if (lane == 0) wsum[wid] = carry;
    __syncthreads();
    if (tid == 0) {
        int c = 0;
        #pragma unroll
        for (int i = 0; i < 8; i++) c += wsum[i];
        s_carry = c;
    }
    __syncthreads();

    int i = b * 256 + tid;
    int v = (i < NN) ? d_count[i] : 0;
    int s = v;
    #pragma unroll
    for (int off = 1; off < 32; off <<= 1) {
        int t = __shfl_up_sync(0xffffffffu, s, off);
        if (lane >= off) s += t;
    }
    if (lane == 31) wsum[wid] = s;
    __syncthreads();
    if (tid < 8) {
        int t = wsum[tid];
        #pragma unroll
        for (int off = 1; off < 8; off <<= 1) {
            int u = __shfl_up_sync(0xffu, t, off);
            if (tid >= off) t += u;
        }
        wsum[tid] = t;
    }
    __syncthreads();
    int wexcl = wid ? wsum[wid - 1] : 0;
    if (i < NN) {
        d_offsets[i] = s_carry + wexcl + s - v;
        d_dis[i] = rsqrtf(d_degw[i] + 2.0f);
    }
    if (b == 0 && tid == 0) d_offsets[NN] = NE;
}

// ---------------- 2: fused scatter + qkv --------------------------------------
__global__ void scatter_qkv_kernel(const int* __restrict__ ei, const float* __restrict__ ea,
                                   const float* __restrict__ x,
                                   const float* __restrict__ Wq, const float* __restrict__ bq,
                                   const float* __restrict__ Wk, const float* __restrict__ bk,
                                   const float* __restrict__ Wv, const float* __restrict__ bv,
                                   const float* __restrict__ Wsk, const float* __restrict__ bsk) {
    int b = blockIdx.x;
    if (b < SCAT_BLOCKS) {
        int e = b * 256 + threadIdx.x;
        if (e < NN) { d_count[e] = 0; d_degw[e] = 0.f; }   // reset for next replay
        if (e < NE) {
            int src = ei[e], dst = ei[NE + e];
            int pos = d_offsets[dst] + atomicAdd(&d_cursor[dst], 1);
            float ax = ea[2 * e], ay = ea[2 * e + 1];
            float4 pk;
            pk.x = __int_as_float(src);
            pk.y = ax;
            pk.z = ay;
            pk.w = d_dis[src] * ay;
            d_csr[pos] = pk;
        }
    } else {
        int lane = threadIdx.x & 31;
        int warp = ((b - SCAT_BLOCKS) * 256 + threadIdx.x) >> 5;
        const int nwarps = QKV_BLOCKS * 8;
        float wq[8], wk[8], wv[8], ws[8];
        #pragma unroll
        for (int i = 0; i < 8; i++) {
            wq[i] = Wq[i * 32 + lane];
            wk[i] = Wk[i * 32 + lane];
            wv[i] = Wv[i * 32 + lane];
            ws[i] = Wsk[i * 32 + lane];
        }
        float bqv = bq[lane], bkv = bk[lane], bvv = bv[lane], bsv = bsk[lane];
        const float QS = 0.25f * 1.4426950408889634f;  // 1/sqrt(16) * log2(e)
        int h = lane >> 4, c = lane & 15;
        int half = c >> 3, j = c & 7;

        for (int n = warp; n < NN; n += nwarps) {
            float x0 = x[n * 64 + lane];
            float x1 = x[n * 64 + 32 + lane];
            #pragma unroll
            for (int bb = 0; bb < 8; bb++) {
                float aq = bqv, ak = bkv, av = bvv, asv = bsv;
                #pragma unroll
                for (int i = 0; i < 8; i++) {
                    const int f = bb * 8 + i;
                    float xv = __shfl_sync(0xffffffffu, (f < 32) ? x0 : x1, f & 31);
                    aq += xv * wq[i]; ak += xv * wk[i]; av += xv * wv[i]; asv += xv * ws[i];
                }
                int pairIdx = bb * 2 + h;
                int vlane = pairIdx * 2 + half;   // owning lane in attn
                d_Qh[n * 256 + vlane * 8 + j] = __float2half(aq * QS);
                d_KV[n * 512 + vlane * 8 + j]       = __float2half(ak);
                d_KV[n * 512 + 256 + vlane * 8 + j] = __float2half(av);
                d_H[n * 256 + vlane * 8 + j] = asv;
            }
        }
    }
}

// ---------------- 3: attention (PROFILED SLOT) --------------------------------
// One warp per dst, whole warp per edge. lane = pair*2 + half owns 8 channels.
// KV row loads: base[lane] (K) and base[32+lane] (V) -> fully coalesced 512B.
__global__ void __launch_bounds__(256, 3) attn_kernel(const float* __restrict__ We) {
    int tid = blockIdx.x * blockDim.x + threadIdx.x;
    int dst = tid >> 5;
    if (dst >= NN) return;
    int lane = threadIdx.x & 31;
    int pair = lane >> 1, half = lane & 1;
    int cbase = ((pair & 1) << 4) + half * 8;   // channel base within HC32

    // q: 8 halves, coalesced
    uint4 qu = ((const uint4*)&d_Qh[dst * 256])[lane];
    __half2 qh[4] = { h2(qu.x), h2(qu.y), h2(qu.z), h2(qu.w) };

    // per-lane partial q . We0 / q . We1 over this lane's 8 channels
    float qw0p = 0.f, qw1p = 0.f;
    #pragma unroll
    for (int i = 0; i < 4; i++) {
        float2 qf = __half22float2(qh[i]);
        qw0p += qf.x * We[cbase + 2 * i]      + qf.y * We[cbase + 2 * i + 1];
        qw1p += qf.x * We[32 + cbase + 2 * i] + qf.y * We[32 + cbase + 2 * i + 1];
    }

    __half2 acch[4];
    #pragma unroll
    for (int i = 0; i < 4; i++) acch[i] = __float2half2_rn(0.f);
    float sax = 0.f, say = 0.f, z = 0.f;

    int start = d_offsets[dst], end = d_offsets[dst + 1];
    for (int e = start; e < end; e += 2) {
        float4 cA = d_csr[e];
        bool hasB = (e + 1 < end);
        float4 cB = d_csr[hasB ? e + 1 : e];
        int srcA = __float_as_int(cA.x);
        int srcB = __float_as_int(cB.x);
        const uint4* bA = (const uint4*)&d_KV[srcA * 512];
        uint4 kaA = bA[lane], vaA = bA[32 + lane];
        const uint4* bB = (const uint4*)&d_KV[srcB * 512];
        uint4 kaB = bB[lane], vaB = bB[32 + lane];

        // logits: partial dot over 8 channels + e-term, complete via shfl_xor(1)
        __half2 dA = __float2half2_rn(0.f);
        dA = __hfma2(qh[0], h2(kaA.x), dA);
        dA = __hfma2(qh[1], h2(kaA.y), dA);
        dA = __hfma2(qh[2], h2(kaA.z), dA);
        dA = __hfma2(qh[3], h2(kaA.w), dA);
        float2 fA = __half22float2(dA);
        float spA = fA.x + fA.y + cA.y * qw0p + cA.z * qw1p;

        __half2 dB = __float2half2_rn(0.f);
        dB = __hfma2(qh[0], h2(kaB.x), dB);
        dB = __hfma2(qh[1], h2(kaB.y), dB);
        dB = __hfma2(qh[2], h2(kaB.z), dB);
        dB = __hfma2(qh[3], h2(kaB.w), dB);
        float2 fB = __half22float2(dB);
        float spB = fB.x + fB.y + cB.y * qw0p + cB.z * qw1p;

        float sA = spA + __shfl_xor_sync(0xffffffffu, spA, 1);
        float sB = spB + __shfl_xor_sync(0xffffffffu, spB, 1);
        float pA = ex2f(sA);
        float pB = hasB ? ex2f(sB) : 0.f;

        z += pA + pB;
        sax = fmaf(pA, cA.y, sax); sax = fmaf(pB, cB.y, sax);
        say = fmaf(pA, cA.z, say); say = fmaf(pB, cB.z, say);

        __half2 pa2 = __float2half2_rn(pA);
        __half2 pb2 = __float2half2_rn(pB);
        acch[0] = __hfma2(pa2, h2(vaA.x), acch[0]);
        acch[1] = __hfma2(pa2, h2(vaA.y), acch[1]);
        acch[2] = __hfma2(pa2, h2(vaA.z), acch[2]);
        acch[3] = __hfma2(pa2, h2(vaA.w), acch[3]);
        acch[0] = __hfma2(pb2, h2(vaB.x), acch[0]);
        acch[1] = __hfma2(pb2, h2(vaB.y), acch[1]);
        acch[2] = __hfma2(pb2, h2(vaB.z), acch[2]);
        acch[3] = __hfma2(pb2, h2(vaB.w), acch[3]);
    }

    // epilogue: each lane finishes its own 8 channels
    float rz = (z > 0.f) ? 1.0f / z : 0.f;
    float f[8];
    #pragma unroll
    for (int i = 0; i < 4; i++) {
        float2 t = __half22float2(acch[i]);
        f[2 * i] = t.x; f[2 * i + 1] = t.y;
    }
    float* Hp = &d_H[dst * 256 + lane * 8];
    float o[8];
    #pragma unroll
    for (int j = 0; j < 8; j++) {
        float w0 = We[cbase + j], w1 = We[32 + cbase + j];
        float a = f[j] + sax * w0 + say * w1;
        float t = fmaf(a, rz, Hp[j]);
        o[j] = (t > 0.f) ? t : 0.1f * (__expf(t) - 1.0f);
    }
    ((float4*)Hp)[0] = make_float4(o[0], o[1], o[2], o[3]);
    ((float4*)Hp)[1] = make_float4(o[4], o[5], o[6], o[7]);
}

// ---------------- 4: hw = h @ Wg, 4 nodes/warp (+ cursor reset) ---------------
// d_H flat index = vlane*8+j with vlane=(band*2+head)*2+half, j -> channel.
// Wg row for flat t: band = (t>>5)&7? No: flat = ((b*2+h)*2+half)*8+j ->
//   b = t>>5, h=(t>>4)&1, half=(t>>3)&1, j=t&7 -> Wg row = b*32 + h*16 + half*8 + j
//   = (t & ~31)... b*32 = t>>5<<5; h*16+half*8+j = ((t>>4)&1)*16+((t>>3)&1)*8+(t&7) = t&31.
// So flat index == Wg row index. Direct match, no permutation needed.
__global__ void hw_kernel(const float* __restrict__ Wg) {
    __shared__ float wgs[256 * 32];
    int gid = blockIdx.x * blockDim.x + threadIdx.x;
    if (gid < NN) d_cursor[gid] = 0;   // reset for next replay's scatter
    for (int idx = threadIdx.x; idx < 8192; idx += blockDim.x)
        wgs[idx] = Wg[idx];
    __syncthreads();
    int lane = threadIdx.x & 31;
    int warp = gid >> 5;
    int nwarps = (gridDim.x * blockDim.x) >> 5;
    for (int n0 = warp * 4; n0 < NN; n0 += nwarps * 4) {
        const float4* H0 = (const float4*)&d_H[n0 * 256];
        const float4* H1 = (const float4*)&d_H[(n0 + 1) * 256];
        const float4* H2 = (const float4*)&d_H[(n0 + 2) * 256];
        const float4* H3 = (const float4*)&d_H[(n0 + 3) * 256];
        float a0 = 0.f, a1 = 0.f, a2 = 0.f, a3 = 0.f;
        #pragma unroll 8
        for (int c = 0; c < 64; c++) {
            float w0 = wgs[(4 * c + 0) * 32 + lane];
            float w1 = wgs[(4 * c + 1) * 32 + lane];
            float w2 = wgs[(4 * c + 2) * 32 + lane];
            float w3 = wgs[(4 * c + 3) * 32 + lane];
            float4 h0 = H0[c], h1 = H1[c], h2v = H2[c], h3 = H3[c];
            a0 += h0.x * w0 + h0.y * w1 + h0.z * w2 + h0.w * w3;
            a1 += h1.x * w0 + h1.y * w1 + h1.z * w2 + h1.w * w3;
            a2 += h2v.x * w0 + h2v.y * w1 + h2v.z * w2 + h2v.w * w3;
            a3 += h3.x * w0 + h3.y * w1 + h3.z * w2 + h3.w * w3;
        }
        d_HW[n0 * 32 + lane] = a0;
        d_HW[(n0 + 1) * 32 + lane] = a1;
        d_HW[(n0 + 2) * 32 + lane] = a2;
        d_HW[(n0 + 3) * 32 + lane] = a3;
    }
}

// ---------------- 5: final normalized propagation -----------------------------
__global__ void final_kernel(const float* __restrict__ bg, float* __restrict__ out) {
    int lane = threadIdx.x & 31;
    int dst = (blockIdx.x * blockDim.x + threadIdx.x) >> 5;
    if (dst >= NN) return;
    float dd = d_dis[dst];
    float acc = 2.0f * dd * d_HW[dst * 32 + lane];  // self loop
    int start = d_offsets[dst], end = d_offsets[dst + 1];
    int last = end - 1;
    for (int t = start; t < end; t += 4) {
        float4 c0 = d_csr[t];
        float4 c1 = d_csr[min(t + 1, last)];
        float4 c2 = d_csr[min(t + 2, last)];
        float4 c3 = d_csr[min(t + 3, last)];
        float w0 = c0.w;
        float w1 = (t + 1 < end) ? c1.w : 0.f;
        float w2 = (t + 2 < end) ? c2.w : 0.f;
        float w3 = (t + 3 < end) ? c3.w : 0.f;
        float v0 = d_HW[__float_as_int(c0.x) * 32 + lane];
        float v1 = d_HW[__float_as_int(c1.x) * 32 + lane];
        float v2 = d_HW[__float_as_int(c2.x) * 32 + lane];
        float v3 = d_HW[__float_as_int(c3.x) * 32 + lane];
        acc = fmaf(w0, v0, acc);
        acc = fmaf(w1, v1, acc);
        acc = fmaf(w2, v2, acc);
        acc = fmaf(w3, v3, acc);
    }
    out[dst * 32 + lane] = bg[lane] + dd * acc;
}

// ---------------- launch -----------------------------------------------------
extern "C" void kernel_launch(void* const* d_in, const int* in_sizes, int n_in,
                              void* d_out, int out_size) {
    const float* x   = (const float*)d_in[0];
    const float* ea  = (const float*)d_in[1];
    const float* Wq  = (const float*)d_in[2];
    const float* bq  = (const float*)d_in[3];
    const float* Wk  = (const float*)d_in[4];
    const float* bk  = (const float*)d_in[5];
    const float* Wv  = (const float*)d_in[6];
    const float* bv  = (const float*)d_in[7];
    const float* We  = (const float*)d_in[8];
    const float* Wsk = (const float*)d_in[9];
    const float* bsk = (const float*)d_in[10];
    const float* Wg  = (const float*)d_in[11];
    const float* bg  = (const float*)d_in[12];
    const int*   ei  = (const int*)d_in[13];
    float* out = (float*)d_out;

    hist_kernel<<<SCAT_BLOCKS, 256>>>(ei, ea);                       // 0
    scan_fused<<<NB, 256>>>();                                       // 1
    scatter_qkv_kernel<<<SCAT_BLOCKS + QKV_BLOCKS, 256>>>(           // 2
        ei, ea, x, Wq, bq, Wk, bk, Wv, bv, Wsk, bsk);
    attn_kernel<<<(NN * 32 + 255) / 256, 256>>>(We);                 // 3 (profiled)
    hw_kernel<<<296, 256>>>(Wg);                                     // 4
    final_kernel<<<(NN * 32 + 255) / 256, 256>>>(bg, out);           // 5
}